// round 14
// baseline (speedup 1.0000x reference)
#include <cuda_runtime.h>

// Problem constants: N=100000, E=3200000, F_IN=256, HID=16, C=16, K=2
#define MAXN 131072
#define MAXE 3200000

// packed f32x2 FMA (FFMA2) — ptxas never emits this from C++, PTX only
#define FMA_F32X2(d, a, b, c) \
    asm("fma.rn.f32x2 %0, %1, %2, %3;" : "=l"(d) : "l"(a), "l"(b), "l"(c))
#define PACK_F32X2(out, lo, hi) \
    asm("mov.b64 %0, {%1, %2};" : "=l"(out) : "f"(lo), "f"(hi))
#define UNPACK_F32X2(lo, hi, in) \
    asm("mov.b64 {%0, %1}, %2;" : "=f"(lo), "=f"(hi) : "l"(in))

// ---------------- device scratch ----------------
__device__ int   g_is64;
__device__ int   g_deg [MAXN];
__device__ int   g_off [MAXN];
__device__ int   g_cur [MAXN];
__device__ int   g_bsum[512];
__device__ int   g_boff[512];
__device__ float g_dinv[MAXN];
__device__ float g_h1  [MAXN * 32];   // conv1 init features, pre-scaled by dinv[src]
__device__ float g_agg1[MAXN * 32];   // conv1 root+bias (accumulator init)
__device__ float g_hfs [MAXN * 16];   // hfeat * dinv (source side for gather2)
__device__ float g_aggr[MAXN * 16];   // conv2 raw aggregation
__device__ float g_W1  [256 * 64];    // cols 0..31 = init (k0,k1), 32..63 = root
__device__ float g_W2  [16 * 64];
__device__ float g_b1  [32];
__device__ float g_b2  [32];
__device__ int   g_csrs[MAXE];        // dst-sorted src ids
__device__ int2  g_sd  [MAXE];        // decoded {src, dst} (written by k_deg)

// ---------------- merged: zero deg + dtype detect + weight packing ----------
__global__ void k_prepzero(const int* __restrict__ ei, int n,
                           const float* __restrict__ iw1, const float* __restrict__ rw1,
                           const float* __restrict__ b1,
                           const float* __restrict__ iw2, const float* __restrict__ rw2,
                           const float* __restrict__ b2) {
    int i = blockIdx.x * 256 + threadIdx.x;
    if (i < n) g_deg[i] = 0;
    if (i == 0) {
        int ok = 1;
        #pragma unroll 1
        for (int j = 0; j < 64; j++)
            if (ei[2 * j + 1] != 0) { ok = 0; break; }
        g_is64 = ok;
    }
    if (i < 16384) {
        int f = i >> 6, c = i & 63;
        if (c < 32) { int k = c >> 4, o = c & 15; g_W1[i] = iw1[k * 4096 + f * 16 + o]; }
        else        { int cc = c - 32; int k = cc >> 4, o = cc & 15; g_W1[i] = rw1[k * 4096 + f * 16 + o]; }
    } else if (i < 16384 + 1024) {
        int j = i - 16384;
        int f = j >> 6, c = j & 63;
        if (c < 32) { int k = c >> 4, o = c & 15; g_W2[j] = iw2[k * 256 + f * 16 + o]; }
        else        { int cc = c - 32; int k = cc >> 4, o = cc & 15; g_W2[j] = rw2[k * 256 + f * 16 + o]; }
    } else if (i < 16384 + 1024 + 32) {
        int j = i - 16384 - 1024; g_b1[j] = b1[j];
    } else if (i < 16384 + 1024 + 64) {
        int j = i - 16384 - 1024 - 32; g_b2[j] = b2[j];
    }
}

// degree count + decode edge list into sequential int2 records
__global__ void k_deg(const int* __restrict__ ei, long long E) {
    long long t = blockIdx.x * 256LL + threadIdx.x;
    if (t >= E) return;
    int is64 = g_is64;
    int s = is64 ? ei[t << 1] : ei[t];
    long long dp = E + t;
    int d = is64 ? ei[dp << 1] : ei[dp];
    g_sd[t] = make_int2(s, d);
    atomicAdd(&g_deg[d], 1);
}

__global__ void k_dinv(int n) {
    int i = blockIdx.x * 256 + threadIdx.x;
    if (i >= n) return;
    int d = g_deg[i];
    g_dinv[i] = (d > 0) ? rsqrtf((float)d) : 0.0f;
}

// ---------------- GEMM1: x[N,256] @ W1[256,64] -------------------------------
// Reg-tiled 4x8 per thread, FFMA2, XOR-swizzled transpose (conflict-free).
// NO double-buffer: minimize registers, maximize occupancy (4 blocks/SM).
__global__ void __launch_bounds__(256, 4) k_gemm1(const float* __restrict__ x, int nNodes) {
    __shared__ float sxT[32][132];   // [k][row swizzled], padded
    __shared__ float sw [32][64];    // [k][col]
    int tid = threadIdx.x;
    int base = blockIdx.x * 128;
    int tx = tid & 7, ty = tid >> 3;

    unsigned long long acc2[4][4];
    #pragma unroll
    for (int i = 0; i < 4; i++)
        #pragma unroll
        for (int j = 0; j < 4; j++) acc2[i][j] = 0ULL;

    int lr  = tid >> 3;   // 0..31 (row within x-load slice)
    int lc4 = tid & 7;    // float4 col within 32-chunk
    int ssw = (lc4 >> 1) << 2;   // store-side swizzle group

    int wk0 = tid >> 4, wc0 = (tid & 15) * 4;
    int wk1 = (tid + 256) >> 4;

    for (int kk = 0; kk < 8; kk++) {
        // W chunk
        *reinterpret_cast<float4*>(&sw[wk0][wc0]) =
            *reinterpret_cast<const float4*>(g_W1 + (kk * 32 + wk0) * 64 + wc0);
        *reinterpret_cast<float4*>(&sw[wk1][wc0]) =
            *reinterpret_cast<const float4*>(g_W1 + (kk * 32 + wk1) * 64 + wc0);
        // X chunk transposed with conflict-free swizzle
        #pragma unroll
        for (int q = 0; q < 4; q++) {
            int r = lr + q * 32;
            int n = base + r;
            float4 v = make_float4(0.f, 0.f, 0.f, 0.f);
            if (n < nNodes)
                v = *reinterpret_cast<const float4*>(x + (long long)n * 256 + kk * 32 + lc4 * 4);
            int rs = r ^ ssw;
            sxT[lc4 * 4 + 0][rs] = v.x;
            sxT[lc4 * 4 + 1][rs] = v.y;
            sxT[lc4 * 4 + 2][rs] = v.z;
            sxT[lc4 * 4 + 3][rs] = v.w;
        }
        __syncthreads();

        #pragma unroll
        for (int k = 0; k < 32; k++) {
            int rs = (ty * 4) ^ (((k >> 3) & 3) << 2);
            float4 xv = *reinterpret_cast<const float4*>(&sxT[k][rs]);
            ulonglong2 wa = *reinterpret_cast<const ulonglong2*>(&sw[k][tx * 8]);
            ulonglong2 wb = *reinterpret_cast<const ulonglong2*>(&sw[k][tx * 8 + 4]);
            float xs[4] = {xv.x, xv.y, xv.z, xv.w};
            #pragma unroll
            for (int i = 0; i < 4; i++) {
                unsigned long long xp;
                PACK_F32X2(xp, xs[i], xs[i]);
                FMA_F32X2(acc2[i][0], xp, wa.x, acc2[i][0]);
                FMA_F32X2(acc2[i][1], xp, wa.y, acc2[i][1]);
                FMA_F32X2(acc2[i][2], xp, wb.x, acc2[i][2]);
                FMA_F32X2(acc2[i][3], xp, wb.y, acc2[i][3]);
            }
        }
        __syncthreads();
    }

    // epilogue: unpack; init cols scaled by dinv[row]; root cols + bias
    int c = tx * 8;
    #pragma unroll
    for (int i = 0; i < 4; i++) {
        int n = base + ty * 4 + i;
        if (n >= nNodes) break;
        float a[8];
        #pragma unroll
        for (int j = 0; j < 4; j++) UNPACK_F32X2(a[2 * j], a[2 * j + 1], acc2[i][j]);
        if (c < 32) {
            float s = g_dinv[n];
            float4* o = reinterpret_cast<float4*>(g_h1 + (long long)n * 32 + c);
            o[0] = make_float4(a[0] * s, a[1] * s, a[2] * s, a[3] * s);
            o[1] = make_float4(a[4] * s, a[5] * s, a[6] * s, a[7] * s);
        } else {
            int cc = c - 32;
            float4* o = reinterpret_cast<float4*>(g_agg1 + (long long)n * 32 + cc);
            o[0] = make_float4(a[0] + g_b1[cc],     a[1] + g_b1[cc + 1],
                               a[2] + g_b1[cc + 2], a[3] + g_b1[cc + 3]);
            o[1] = make_float4(a[4] + g_b1[cc + 4], a[5] + g_b1[cc + 5],
                               a[6] + g_b1[cc + 6], a[7] + g_b1[cc + 7]);
        }
    }
}

// ---------------- 3-phase exclusive scan of g_deg -> g_off/g_cur ----------
__global__ void k_scanA(int n) {
    __shared__ int sm[256];
    int base = blockIdx.x * 1024;
    int t = threadIdx.x;
    int s = 0;
    #pragma unroll
    for (int j = 0; j < 4; j++) {
        int i = base + t * 4 + j;
        if (i < n) s += g_deg[i];
    }
    sm[t] = s; __syncthreads();
    #pragma unroll
    for (int o = 128; o > 0; o >>= 1) {
        if (t < o) sm[t] += sm[t + o];
        __syncthreads();
    }
    if (t == 0) g_bsum[blockIdx.x] = sm[0];
}
__global__ void k_scanB(int nb) {
    __shared__ int sm[512];
    int t = threadIdx.x;
    int v0 = (t < nb) ? g_bsum[t] : 0;
    sm[t] = v0; __syncthreads();
    #pragma unroll
    for (int o = 1; o < 512; o <<= 1) {
        int v = (t >= o) ? sm[t - o] : 0;
        __syncthreads();
        sm[t] += v;
        __syncthreads();
    }
    if (t < nb) g_boff[t] = sm[t] - v0;    // exclusive
}
__global__ void k_scanC(int n) {
    __shared__ int sm[256];
    int base = blockIdx.x * 1024;
    int t = threadIdx.x;
    int d[4]; int s = 0;
    #pragma unroll
    for (int j = 0; j < 4; j++) {
        int i = base + t * 4 + j;
        d[j] = (i < n) ? g_deg[i] : 0;
        s += d[j];
    }
    sm[t] = s; __syncthreads();
    #pragma unroll
    for (int o = 1; o < 256; o <<= 1) {
        int v = (t >= o) ? sm[t - o] : 0;
        __syncthreads();
        sm[t] += v;
        __syncthreads();
    }
    int excl = sm[t] - s + g_boff[blockIdx.x];
    #pragma unroll
    for (int j = 0; j < 4; j++) {
        int i = base + t * 4 + j;
        if (i < n) { g_off[i] = excl; g_cur[i] = excl; excl += d[j]; }
    }
}

// ---------------- fill CSR (src only, 4B/edge) from decoded pairs ----------
__global__ void k_fill(long long E) {
    long long t = blockIdx.x * 256LL + threadIdx.x;
    if (t >= E) return;
    int2 sd = g_sd[t];
    int pos = atomicAdd(&g_cur[sd.y], 1);
    g_csrs[pos] = sd.x;
}

// ---------------- gather1: acc = dinv[n]*sum(h1[src]); +root+bias; relu; mean --
__global__ void __launch_bounds__(256) k_gather1(float* __restrict__ hfeat, int nNodes) {
    int t = blockIdx.x * 256 + threadIdx.x;
    int node = t >> 3;
    bool valid = node < nNodes;
    int n = valid ? node : (nNodes - 1);
    int part = t & 7;
    int beg = g_off[n];
    int end = beg + g_deg[n];
    float4 rb = *reinterpret_cast<const float4*>(g_agg1 + ((long long)n << 5) + (part << 2));
    float din = g_dinv[n];
    float4 acc = make_float4(0.f, 0.f, 0.f, 0.f);
    int i = beg;
    for (; i + 4 <= end; i += 4) {
        int s0 = g_csrs[i], s1 = g_csrs[i + 1], s2 = g_csrs[i + 2], s3 = g_csrs[i + 3];
        float4 v0 = *reinterpret_cast<const float4*>(g_h1 + ((long long)s0 << 5) + (part << 2));
        float4 v1 = *reinterpret_cast<const float4*>(g_h1 + ((long long)s1 << 5) + (part << 2));
        float4 v2 = *reinterpret_cast<const float4*>(g_h1 + ((long long)s2 << 5) + (part << 2));
        float4 v3 = *reinterpret_cast<const float4*>(g_h1 + ((long long)s3 << 5) + (part << 2));
        acc.x += v0.x + v1.x + v2.x + v3.x;
        acc.y += v0.y + v1.y + v2.y + v3.y;
        acc.z += v0.z + v1.z + v2.z + v3.z;
        acc.w += v0.w + v1.w + v2.w + v3.w;
    }
    for (; i < end; i++) {
        int s = g_csrs[i];
        float4 v = *reinterpret_cast<const float4*>(g_h1 + ((long long)s << 5) + (part << 2));
        acc.x += v.x; acc.y += v.y; acc.z += v.z; acc.w += v.w;
    }
    acc.x = fmaxf(rb.x + din * acc.x, 0.f);
    acc.y = fmaxf(rb.y + din * acc.y, 0.f);
    acc.z = fmaxf(rb.z + din * acc.z, 0.f);
    acc.w = fmaxf(rb.w + din * acc.w, 0.f);
    float ox = 0.5f * (acc.x + __shfl_xor_sync(0xffffffffu, acc.x, 4));
    float oy = 0.5f * (acc.y + __shfl_xor_sync(0xffffffffu, acc.y, 4));
    float oz = 0.5f * (acc.z + __shfl_xor_sync(0xffffffffu, acc.z, 4));
    float ow = 0.5f * (acc.w + __shfl_xor_sync(0xffffffffu, acc.w, 4));
    if (valid && part < 4) {
        reinterpret_cast<float4*>(hfeat)[((long long)n << 2) + part] =
            make_float4(ox, oy, oz, ow);
        reinterpret_cast<float4*>(g_hfs)[((long long)n << 2) + part] =
            make_float4(ox * din, oy * din, oz * din, ow * din);
    }
}

// ---------------- gather2: aggr[n] = dinv[n] * sum(hfs[src]) ----------------
__global__ void __launch_bounds__(256) k_gather2(int nNodes) {
    int t = blockIdx.x * 256 + threadIdx.x;
    int n = t >> 2;
    if (n >= nNodes) return;
    int part = t & 3;
    int beg = g_off[n];
    int end = beg + g_deg[n];
    float din = g_dinv[n];
    float4 acc = make_float4(0.f, 0.f, 0.f, 0.f);
    int i = beg;
    for (; i + 4 <= end; i += 4) {
        int s0 = g_csrs[i], s1 = g_csrs[i + 1], s2 = g_csrs[i + 2], s3 = g_csrs[i + 3];
        float4 v0 = *reinterpret_cast<const float4*>(g_hfs + ((long long)s0 << 4) + (part << 2));
        float4 v1 = *reinterpret_cast<const float4*>(g_hfs + ((long long)s1 << 4) + (part << 2));
        float4 v2 = *reinterpret_cast<const float4*>(g_hfs + ((long long)s2 << 4) + (part << 2));
        float4 v3 = *reinterpret_cast<const float4*>(g_hfs + ((long long)s3 << 4) + (part << 2));
        acc.x += v0.x + v1.x + v2.x + v3.x;
        acc.y += v0.y + v1.y + v2.y + v3.y;
        acc.z += v0.z + v1.z + v2.z + v3.z;
        acc.w += v0.w + v1.w + v2.w + v3.w;
    }
    for (; i < end; i++) {
        int s = g_csrs[i];
        float4 v = *reinterpret_cast<const float4*>(g_hfs + ((long long)s << 4) + (part << 2));
        acc.x += v.x; acc.y += v.y; acc.z += v.z; acc.w += v.w;
    }
    reinterpret_cast<float4*>(g_aggr)[((long long)n << 2) + part] =
        make_float4(acc.x * din, acc.y * din, acc.z * din, acc.w * din);
}

// ---------------- final: GEMM2 + root + bias, K-mean, log_softmax ----------------
__global__ void __launch_bounds__(256) k_final(const float* __restrict__ hfeat,
                                               float* __restrict__ out, int nNodes) {
    __shared__ float sw[1024];
    __shared__ float sb[32];
    for (int i = threadIdx.x; i < 1024; i += 256) sw[i] = g_W2[i];
    if (threadIdx.x < 32) sb[threadIdx.x] = g_b2[threadIdx.x];
    __syncthreads();
    int n = blockIdx.x * 256 + threadIdx.x;
    if (n >= nNodes) return;

    float hr[16], ag[16];
    const float4* hp = reinterpret_cast<const float4*>(hfeat + (long long)n * 16);
    const float4* ap = reinterpret_cast<const float4*>(g_aggr) + (long long)n * 4;
    #pragma unroll
    for (int j = 0; j < 4; j++) {
        float4 h4 = hp[j], a4 = ap[j];
        hr[4 * j] = h4.x; hr[4 * j + 1] = h4.y; hr[4 * j + 2] = h4.z; hr[4 * j + 3] = h4.w;
        ag[4 * j] = a4.x; ag[4 * j + 1] = a4.y; ag[4 * j + 2] = a4.z; ag[4 * j + 3] = a4.w;
    }

    float l[16];
    #pragma unroll
    for (int o = 0; o < 16; o++) l[o] = 0.f;
    #pragma unroll
    for (int k = 0; k < 2; k++) {
        float acc[16];
        #pragma unroll
        for (int o = 0; o < 16; o++) acc[o] = sb[k * 16 + o];
        #pragma unroll
        for (int f = 0; f < 16; f++) {
            float av = ag[f], hv = hr[f];
            const float* wi = sw + f * 64 + k * 16;       // init
            const float* wr = wi + 32;                    // root
            #pragma unroll
            for (int o = 0; o < 16; o++)
                acc[o] += av * wi[o] + hv * wr[o];
        }
        #pragma unroll
        for (int o = 0; o < 16; o++) l[o] += 0.5f * acc[o];
    }

    float m = l[0];
    #pragma unroll
    for (int i = 1; i < 16; i++) m = fmaxf(m, l[i]);
    float s = 0.f;
    #pragma unroll
    for (int i = 0; i < 16; i++) s += expf(l[i] - m);
    float lg = m + logf(s);
    float4* o4 = reinterpret_cast<float4*>(out + (long long)n * 16);
    #pragma unroll
    for (int j = 0; j < 4; j++)
        o4[j] = make_float4(l[4 * j] - lg, l[4 * j + 1] - lg,
                            l[4 * j + 2] - lg, l[4 * j + 3] - lg);
}

// ---------------- launch ----------------
extern "C" void kernel_launch(void* const* d_in, const int* in_sizes, int n_in,
                              void* d_out, int out_size) {
    const float* x   = (const float*)d_in[0];
    const int*   ei  = (const int*)d_in[1];
    const float* iw1 = (const float*)d_in[2];
    const float* rw1 = (const float*)d_in[3];
    const float* b1  = (const float*)d_in[4];
    const float* iw2 = (const float*)d_in[5];
    const float* rw2 = (const float*)d_in[6];
    const float* b2  = (const float*)d_in[7];
    float* out = (float*)d_out;

    int N = in_sizes[0] / 256;
    long long E = in_sizes[1] / 2;
    float* hfeat = out + (long long)N * 16;   // agg_feature region of d_out

    int nbN  = (N + 255) / 256;
    int nbSc = (N + 1023) / 1024;
    int nbE  = (int)((E + 255) / 256);
    int nbG1 = (N * 8 + 255) / 256;
    int nbG2 = (N * 4 + 255) / 256;
    int nbP  = nbN > ((16384 + 1024 + 64 + 255) / 256) ? nbN : ((16384 + 1024 + 64 + 255) / 256);

    k_prepzero<<<nbP, 256>>>(ei, N, iw1, rw1, b1, iw2, rw2, b2);
    k_deg    <<<nbE, 256>>>(ei, E);
    k_dinv   <<<nbN, 256>>>(N);
    k_gemm1  <<<(N + 127) / 128, 256>>>(x, N);
    k_scanA  <<<nbSc, 256>>>(N);
    k_scanB  <<<1, 512>>>(nbSc);
    k_scanC  <<<nbSc, 256>>>(N);
    k_fill   <<<nbE, 256>>>(E);
    k_gather1<<<nbG1, 256>>>(hfeat, N);
    k_gather2<<<nbG2, 256>>>(N);
    k_final  <<<nbN, 256>>>(hfeat, out, N);
}

// round 15
// speedup vs baseline: 1.2152x; 1.2152x over previous
#include <cuda_runtime.h>

// Problem constants: N=100000, E=3200000, F_IN=256, HID=16, C=16, K=2
#define MAXN 131072
#define MAXE 3200000

// packed f32x2 FMA (FFMA2) — ptxas never emits this from C++, PTX only
#define FMA_F32X2(d, a, b, c) \
    asm("fma.rn.f32x2 %0, %1, %2, %3;" : "=l"(d) : "l"(a), "l"(b), "l"(c))
#define PACK_F32X2(out, lo, hi) \
    asm("mov.b64 %0, {%1, %2};" : "=l"(out) : "f"(lo), "f"(hi))
#define UNPACK_F32X2(lo, hi, in) \
    asm("mov.b64 {%0, %1}, %2;" : "=f"(lo), "=f"(hi) : "l"(in))

// ---------------- device scratch ----------------
__device__ int   g_is64;
__device__ int   g_deg [MAXN];
__device__ int   g_off [MAXN];
__device__ int   g_cur [MAXN];
__device__ int   g_bsum[512];
__device__ int   g_boff[512];
__device__ float g_dinv[MAXN];
__device__ float g_h1  [MAXN * 32];   // conv1 init features, pre-scaled by dinv[src]
__device__ float g_agg1[MAXN * 32];   // conv1 root+bias (accumulator init)
__device__ float g_hfs [MAXN * 16];   // hfeat * dinv (source side for gather2)
__device__ float g_aggr[MAXN * 16];   // conv2 raw aggregation
__device__ float g_W1  [256 * 64];    // cols 0..31 = init (k0,k1), 32..63 = root
__device__ float g_W2  [16 * 64];
__device__ float g_b1  [32];
__device__ float g_b2  [32];
__device__ int   g_csrs[MAXE];        // dst-sorted src ids
__device__ int2  g_sd  [MAXE];        // decoded {src, dst} (written by k_deg)

// ---------------- merged: zero deg + dtype detect + weight packing ----------
__global__ void k_prepzero(const int* __restrict__ ei, int n,
                           const float* __restrict__ iw1, const float* __restrict__ rw1,
                           const float* __restrict__ b1,
                           const float* __restrict__ iw2, const float* __restrict__ rw2,
                           const float* __restrict__ b2) {
    int i = blockIdx.x * 256 + threadIdx.x;
    if (i < n) g_deg[i] = 0;
    if (i == 0) {
        int ok = 1;
        #pragma unroll 1
        for (int j = 0; j < 64; j++)
            if (ei[2 * j + 1] != 0) { ok = 0; break; }
        g_is64 = ok;
    }
    if (i < 16384) {
        int f = i >> 6, c = i & 63;
        if (c < 32) { int k = c >> 4, o = c & 15; g_W1[i] = iw1[k * 4096 + f * 16 + o]; }
        else        { int cc = c - 32; int k = cc >> 4, o = cc & 15; g_W1[i] = rw1[k * 4096 + f * 16 + o]; }
    } else if (i < 16384 + 1024) {
        int j = i - 16384;
        int f = j >> 6, c = j & 63;
        if (c < 32) { int k = c >> 4, o = c & 15; g_W2[j] = iw2[k * 256 + f * 16 + o]; }
        else        { int cc = c - 32; int k = cc >> 4, o = cc & 15; g_W2[j] = rw2[k * 256 + f * 16 + o]; }
    } else if (i < 16384 + 1024 + 32) {
        int j = i - 16384 - 1024; g_b1[j] = b1[j];
    } else if (i < 16384 + 1024 + 64) {
        int j = i - 16384 - 1024 - 32; g_b2[j] = b2[j];
    }
}

// degree count + decode edge list into sequential int2 records
__global__ void k_deg(const int* __restrict__ ei, long long E) {
    long long t = blockIdx.x * 256LL + threadIdx.x;
    if (t >= E) return;
    int is64 = g_is64;
    int s = is64 ? ei[t << 1] : ei[t];
    long long dp = E + t;
    int d = is64 ? ei[dp << 1] : ei[dp];
    g_sd[t] = make_int2(s, d);
    atomicAdd(&g_deg[d], 1);
}

__global__ void k_dinv(int n) {
    int i = blockIdx.x * 256 + threadIdx.x;
    if (i >= n) return;
    int d = g_deg[i];
    g_dinv[i] = (d > 0) ? rsqrtf((float)d) : 0.0f;
}

// ---------------- GEMM1: x[N,256] @ W1[256,64] -------------------------------
// 8x8 per-thread tile: rows {base+ty*4..+3, base+128+ty*4..+3}, interleaved
// cols {tx*4..+3 (init), 32+tx*4..+3 (root)}. FFMA2 accumulators.
// sxT stride 260 -> conflict-free swizzled transpose stores; W reads span
// 128B (bank=4*tx) -> conflict-free.
__global__ void __launch_bounds__(256, 2) k_gemm1(const float* __restrict__ x, int nNodes) {
    __shared__ float sxT[32][260];   // [k][row 0..255, swizzled]
    __shared__ float sw [32][64];    // [k][col]
    int tid = threadIdx.x;
    int base = blockIdx.x * 256;
    int tx = tid & 7, ty = tid >> 3;   // ty 0..31

    unsigned long long acc2[2][4][4];  // [rowhalf][row][colpair] (pairs 0-1 init, 2-3 root)
    #pragma unroll
    for (int h = 0; h < 2; h++)
        #pragma unroll
        for (int i = 0; i < 4; i++)
            #pragma unroll
            for (int j = 0; j < 4; j++) acc2[h][i][j] = 0ULL;

    int lr  = tid >> 3;   // 0..31 (row within a 32-row load slice)
    int lc4 = tid & 7;    // float4 col within 32-k chunk
    int ssw = (lc4 >> 1) << 2;     // store-side swizzle: XOR bits 2-3 of row

    int wk0 = tid >> 4, wc0 = (tid & 15) * 4;
    int wk1 = (tid + 256) >> 4;

    for (int kk = 0; kk < 8; kk++) {
        // stage W chunk (32x64)
        *reinterpret_cast<float4*>(&sw[wk0][wc0]) =
            *reinterpret_cast<const float4*>(g_W1 + (kk * 32 + wk0) * 64 + wc0);
        *reinterpret_cast<float4*>(&sw[wk1][wc0]) =
            *reinterpret_cast<const float4*>(g_W1 + (kk * 32 + wk1) * 64 + wc0);
        // stage x chunk transposed: 256 rows x 32 k, 8 slices of 32 rows
        #pragma unroll
        for (int q = 0; q < 8; q++) {
            int r = lr + q * 32;
            int n = base + r;
            float4 v = make_float4(0.f, 0.f, 0.f, 0.f);
            if (n < nNodes)
                v = *reinterpret_cast<const float4*>(x + (long long)n * 256 + kk * 32 + lc4 * 4);
            int rs = r ^ ssw;
            sxT[lc4 * 4 + 0][rs] = v.x;
            sxT[lc4 * 4 + 1][rs] = v.y;
            sxT[lc4 * 4 + 2][rs] = v.z;
            sxT[lc4 * 4 + 3][rs] = v.w;
        }
        __syncthreads();

        #pragma unroll
        for (int k = 0; k < 32; k++) {
            int rs0 = (ty * 4) ^ (((k >> 3) & 3) << 2);      // 16B-aligned
            float4 xv0 = *reinterpret_cast<const float4*>(&sxT[k][rs0]);
            float4 xv1 = *reinterpret_cast<const float4*>(&sxT[k][128 + rs0]);
            ulonglong2 wa = *reinterpret_cast<const ulonglong2*>(&sw[k][tx * 4]);       // init pair
            ulonglong2 wb = *reinterpret_cast<const ulonglong2*>(&sw[k][32 + tx * 4]);  // root pair
            float xs0[4] = {xv0.x, xv0.y, xv0.z, xv0.w};
            float xs1[4] = {xv1.x, xv1.y, xv1.z, xv1.w};
            #pragma unroll
            for (int i = 0; i < 4; i++) {
                unsigned long long xp0, xp1;
                PACK_F32X2(xp0, xs0[i], xs0[i]);
                PACK_F32X2(xp1, xs1[i], xs1[i]);
                FMA_F32X2(acc2[0][i][0], xp0, wa.x, acc2[0][i][0]);
                FMA_F32X2(acc2[0][i][1], xp0, wa.y, acc2[0][i][1]);
                FMA_F32X2(acc2[0][i][2], xp0, wb.x, acc2[0][i][2]);
                FMA_F32X2(acc2[0][i][3], xp0, wb.y, acc2[0][i][3]);
                FMA_F32X2(acc2[1][i][0], xp1, wa.x, acc2[1][i][0]);
                FMA_F32X2(acc2[1][i][1], xp1, wa.y, acc2[1][i][1]);
                FMA_F32X2(acc2[1][i][2], xp1, wb.x, acc2[1][i][2]);
                FMA_F32X2(acc2[1][i][3], xp1, wb.y, acc2[1][i][3]);
            }
        }
        __syncthreads();
    }

    // epilogue: each thread writes init float4 (scaled by dinv) + root float4 (+bias)
    float bb[4];
    #pragma unroll
    for (int q = 0; q < 4; q++) bb[q] = g_b1[tx * 4 + q];
    #pragma unroll
    for (int h = 0; h < 2; h++) {
        #pragma unroll
        for (int i = 0; i < 4; i++) {
            int n = base + h * 128 + ty * 4 + i;
            if (n >= nNodes) continue;
            float a[8];
            #pragma unroll
            for (int j = 0; j < 4; j++) UNPACK_F32X2(a[2 * j], a[2 * j + 1], acc2[h][i][j]);
            float s = g_dinv[n];
            *reinterpret_cast<float4*>(g_h1 + (long long)n * 32 + tx * 4) =
                make_float4(a[0] * s, a[1] * s, a[2] * s, a[3] * s);
            *reinterpret_cast<float4*>(g_agg1 + (long long)n * 32 + tx * 4) =
                make_float4(a[4] + bb[0], a[5] + bb[1], a[6] + bb[2], a[7] + bb[3]);
        }
    }
}

// ---------------- 3-phase exclusive scan of g_deg -> g_off/g_cur ----------
__global__ void k_scanA(int n) {
    __shared__ int sm[256];
    int base = blockIdx.x * 1024;
    int t = threadIdx.x;
    int s = 0;
    #pragma unroll
    for (int j = 0; j < 4; j++) {
        int i = base + t * 4 + j;
        if (i < n) s += g_deg[i];
    }
    sm[t] = s; __syncthreads();
    #pragma unroll
    for (int o = 128; o > 0; o >>= 1) {
        if (t < o) sm[t] += sm[t + o];
        __syncthreads();
    }
    if (t == 0) g_bsum[blockIdx.x] = sm[0];
}
__global__ void k_scanB(int nb) {
    __shared__ int sm[512];
    int t = threadIdx.x;
    int v0 = (t < nb) ? g_bsum[t] : 0;
    sm[t] = v0; __syncthreads();
    #pragma unroll
    for (int o = 1; o < 512; o <<= 1) {
        int v = (t >= o) ? sm[t - o] : 0;
        __syncthreads();
        sm[t] += v;
        __syncthreads();
    }
    if (t < nb) g_boff[t] = sm[t] - v0;    // exclusive
}
__global__ void k_scanC(int n) {
    __shared__ int sm[256];
    int base = blockIdx.x * 1024;
    int t = threadIdx.x;
    int d[4]; int s = 0;
    #pragma unroll
    for (int j = 0; j < 4; j++) {
        int i = base + t * 4 + j;
        d[j] = (i < n) ? g_deg[i] : 0;
        s += d[j];
    }
    sm[t] = s; __syncthreads();
    #pragma unroll
    for (int o = 1; o < 256; o <<= 1) {
        int v = (t >= o) ? sm[t - o] : 0;
        __syncthreads();
        sm[t] += v;
        __syncthreads();
    }
    int excl = sm[t] - s + g_boff[blockIdx.x];
    #pragma unroll
    for (int j = 0; j < 4; j++) {
        int i = base + t * 4 + j;
        if (i < n) { g_off[i] = excl; g_cur[i] = excl; excl += d[j]; }
    }
}

// ---------------- fill CSR (src only, 4B/edge) from decoded pairs ----------
__global__ void k_fill(long long E) {
    long long t = blockIdx.x * 256LL + threadIdx.x;
    if (t >= E) return;
    int2 sd = g_sd[t];
    int pos = atomicAdd(&g_cur[sd.y], 1);
    g_csrs[pos] = sd.x;
}

// ---------------- gather1: acc = dinv[n]*sum(h1[src]); +root+bias; relu; mean --
__global__ void __launch_bounds__(256) k_gather1(float* __restrict__ hfeat, int nNodes) {
    int t = blockIdx.x * 256 + threadIdx.x;
    int node = t >> 3;
    bool valid = node < nNodes;
    int n = valid ? node : (nNodes - 1);
    int part = t & 7;
    int beg = g_off[n];
    int end = beg + g_deg[n];
    float4 rb = *reinterpret_cast<const float4*>(g_agg1 + ((long long)n << 5) + (part << 2));
    float din = g_dinv[n];
    float4 acc = make_float4(0.f, 0.f, 0.f, 0.f);
    int i = beg;
    for (; i + 4 <= end; i += 4) {
        int s0 = g_csrs[i], s1 = g_csrs[i + 1], s2 = g_csrs[i + 2], s3 = g_csrs[i + 3];
        float4 v0 = *reinterpret_cast<const float4*>(g_h1 + ((long long)s0 << 5) + (part << 2));
        float4 v1 = *reinterpret_cast<const float4*>(g_h1 + ((long long)s1 << 5) + (part << 2));
        float4 v2 = *reinterpret_cast<const float4*>(g_h1 + ((long long)s2 << 5) + (part << 2));
        float4 v3 = *reinterpret_cast<const float4*>(g_h1 + ((long long)s3 << 5) + (part << 2));
        acc.x += v0.x + v1.x + v2.x + v3.x;
        acc.y += v0.y + v1.y + v2.y + v3.y;
        acc.z += v0.z + v1.z + v2.z + v3.z;
        acc.w += v0.w + v1.w + v2.w + v3.w;
    }
    for (; i < end; i++) {
        int s = g_csrs[i];
        float4 v = *reinterpret_cast<const float4*>(g_h1 + ((long long)s << 5) + (part << 2));
        acc.x += v.x; acc.y += v.y; acc.z += v.z; acc.w += v.w;
    }
    acc.x = fmaxf(rb.x + din * acc.x, 0.f);
    acc.y = fmaxf(rb.y + din * acc.y, 0.f);
    acc.z = fmaxf(rb.z + din * acc.z, 0.f);
    acc.w = fmaxf(rb.w + din * acc.w, 0.f);
    float ox = 0.5f * (acc.x + __shfl_xor_sync(0xffffffffu, acc.x, 4));
    float oy = 0.5f * (acc.y + __shfl_xor_sync(0xffffffffu, acc.y, 4));
    float oz = 0.5f * (acc.z + __shfl_xor_sync(0xffffffffu, acc.z, 4));
    float ow = 0.5f * (acc.w + __shfl_xor_sync(0xffffffffu, acc.w, 4));
    if (valid && part < 4) {
        reinterpret_cast<float4*>(hfeat)[((long long)n << 2) + part] =
            make_float4(ox, oy, oz, ow);
        reinterpret_cast<float4*>(g_hfs)[((long long)n << 2) + part] =
            make_float4(ox * din, oy * din, oz * din, ow * din);
    }
}

// ---------------- gather2: aggr[n] = dinv[n] * sum(hfs[src]) ----------------
__global__ void __launch_bounds__(256) k_gather2(int nNodes) {
    int t = blockIdx.x * 256 + threadIdx.x;
    int n = t >> 2;
    if (n >= nNodes) return;
    int part = t & 3;
    int beg = g_off[n];
    int end = beg + g_deg[n];
    float din = g_dinv[n];
    float4 acc = make_float4(0.f, 0.f, 0.f, 0.f);
    int i = beg;
    for (; i + 4 <= end; i += 4) {
        int s0 = g_csrs[i], s1 = g_csrs[i + 1], s2 = g_csrs[i + 2], s3 = g_csrs[i + 3];
        float4 v0 = *reinterpret_cast<const float4*>(g_hfs + ((long long)s0 << 4) + (part << 2));
        float4 v1 = *reinterpret_cast<const float4*>(g_hfs + ((long long)s1 << 4) + (part << 2));
        float4 v2 = *reinterpret_cast<const float4*>(g_hfs + ((long long)s2 << 4) + (part << 2));
        float4 v3 = *reinterpret_cast<const float4*>(g_hfs + ((long long)s3 << 4) + (part << 2));
        acc.x += v0.x + v1.x + v2.x + v3.x;
        acc.y += v0.y + v1.y + v2.y + v3.y;
        acc.z += v0.z + v1.z + v2.z + v3.z;
        acc.w += v0.w + v1.w + v2.w + v3.w;
    }
    for (; i < end; i++) {
        int s = g_csrs[i];
        float4 v = *reinterpret_cast<const float4*>(g_hfs + ((long long)s << 4) + (part << 2));
        acc.x += v.x; acc.y += v.y; acc.z += v.z; acc.w += v.w;
    }
    reinterpret_cast<float4*>(g_aggr)[((long long)n << 2) + part] =
        make_float4(acc.x * din, acc.y * din, acc.z * din, acc.w * din);
}

// ---------------- final: GEMM2 + root + bias, K-mean, log_softmax ----------------
__global__ void __launch_bounds__(256) k_final(const float* __restrict__ hfeat,
                                               float* __restrict__ out, int nNodes) {
    __shared__ float sw[1024];
    __shared__ float sb[32];
    for (int i = threadIdx.x; i < 1024; i += 256) sw[i] = g_W2[i];
    if (threadIdx.x < 32) sb[threadIdx.x] = g_b2[threadIdx.x];
    __syncthreads();
    int n = blockIdx.x * 256 + threadIdx.x;
    if (n >= nNodes) return;

    float hr[16], ag[16];
    const float4* hp = reinterpret_cast<const float4*>(hfeat + (long long)n * 16);
    const float4* ap = reinterpret_cast<const float4*>(g_aggr) + (long long)n * 4;
    #pragma unroll
    for (int j = 0; j < 4; j++) {
        float4 h4 = hp[j], a4 = ap[j];
        hr[4 * j] = h4.x; hr[4 * j + 1] = h4.y; hr[4 * j + 2] = h4.z; hr[4 * j + 3] = h4.w;
        ag[4 * j] = a4.x; ag[4 * j + 1] = a4.y; ag[4 * j + 2] = a4.z; ag[4 * j + 3] = a4.w;
    }

    float l[16];
    #pragma unroll
    for (int o = 0; o < 16; o++) l[o] = 0.f;
    #pragma unroll
    for (int k = 0; k < 2; k++) {
        float acc[16];
        #pragma unroll
        for (int o = 0; o < 16; o++) acc[o] = sb[k * 16 + o];
        #pragma unroll
        for (int f = 0; f < 16; f++) {
            float av = ag[f], hv = hr[f];
            const float* wi = sw + f * 64 + k * 16;       // init
            const float* wr = wi + 32;                    // root
            #pragma unroll
            for (int o = 0; o < 16; o++)
                acc[o] += av * wi[o] + hv * wr[o];
        }
        #pragma unroll
        for (int o = 0; o < 16; o++) l[o] += 0.5f * acc[o];
    }

    float m = l[0];
    #pragma unroll
    for (int i = 1; i < 16; i++) m = fmaxf(m, l[i]);
    float s = 0.f;
    #pragma unroll
    for (int i = 0; i < 16; i++) s += expf(l[i] - m);
    float lg = m + logf(s);
    float4* o4 = reinterpret_cast<float4*>(out + (long long)n * 16);
    #pragma unroll
    for (int j = 0; j < 4; j++)
        o4[j] = make_float4(l[4 * j] - lg, l[4 * j + 1] - lg,
                            l[4 * j + 2] - lg, l[4 * j + 3] - lg);
}

// ---------------- launch ----------------
extern "C" void kernel_launch(void* const* d_in, const int* in_sizes, int n_in,
                              void* d_out, int out_size) {
    const float* x   = (const float*)d_in[0];
    const int*   ei  = (const int*)d_in[1];
    const float* iw1 = (const float*)d_in[2];
    const float* rw1 = (const float*)d_in[3];
    const float* b1  = (const float*)d_in[4];
    const float* iw2 = (const float*)d_in[5];
    const float* rw2 = (const float*)d_in[6];
    const float* b2  = (const float*)d_in[7];
    float* out = (float*)d_out;

    int N = in_sizes[0] / 256;
    long long E = in_sizes[1] / 2;
    float* hfeat = out + (long long)N * 16;   // agg_feature region of d_out

    int nbN  = (N + 255) / 256;
    int nbSc = (N + 1023) / 1024;
    int nbE  = (int)((E + 255) / 256);
    int nbG1 = (N * 8 + 255) / 256;
    int nbG2 = (N * 4 + 255) / 256;
    int nbP  = nbN > ((16384 + 1024 + 64 + 255) / 256) ? nbN : ((16384 + 1024 + 64 + 255) / 256);

    k_prepzero<<<nbP, 256>>>(ei, N, iw1, rw1, b1, iw2, rw2, b2);
    k_deg    <<<nbE, 256>>>(ei, E);
    k_dinv   <<<nbN, 256>>>(N);
    k_gemm1  <<<(N + 255) / 256, 256>>>(x, N);
    k_scanA  <<<nbSc, 256>>>(N);
    k_scanB  <<<1, 512>>>(nbSc);
    k_scanC  <<<nbSc, 256>>>(N);
    k_fill   <<<nbE, 256>>>(E);
    k_gather1<<<nbG1, 256>>>(hfeat, N);
    k_gather2<<<nbG2, 256>>>(N);
    k_final  <<<nbN, 256>>>(hfeat, out, N);
}